// round 16
// baseline (speedup 1.0000x reference)
#include <cuda_runtime.h>
#include <cuda/atomic>
#include <math.h>

#define NB     4
#define NPTS   8192
#define NPOINT 409          /* int(8192*0.05) */
#define NG     (NB*NPOINT)  /* 1636 */
#define NBKT   2048         /* counting-sort buckets (11-bit Morton prefix) */
#define RBLK   256
#define NBLK_REP (NB*(NPTS/RBLK))    /* 128 */
#define TOTAL_BLKS (NG + NBLK_REP)   /* 1764 */
#define FTH    128          /* fps threads: 4 warps, 64 pts/lane */

// ---------------- device scratch (no allocations allowed) ----------------
__device__ double g_acc[2];                   // [0]=uniform, [1]=repulsion sum
__device__ float  g_newxyz[NB*NPOINT*3];      // FPS centers
__device__ float4 g_sorted[NB*NPTS];          // Morton-bucketed points (w = orig idx)
__device__ float4 g_pcd4[NB*NPTS];            // original-order points, float4
__device__ int    g_bktoff[NB*(NBKT+1)];      // bucket start offsets + sentinel
__device__ unsigned g_done;                   // completion counter

// exact-rounding distance (FPS argmax must match reference exactly)
__device__ __forceinline__ float sqdist_rn(float ax, float ay, float az,
                                           float bx, float by, float bz) {
    float dx = __fadd_rn(ax, -bx);
    float dy = __fadd_rn(ay, -by);
    float dz = __fadd_rn(az, -bz);
    return __fadd_rn(__fadd_rn(__fmul_rn(dx, dx), __fmul_rn(dy, dy)),
                     __fmul_rn(dz, dz));
}
// fast distance (FMA) — continuous-use sites only
__device__ __forceinline__ float sqdist_f(float ax, float ay, float az,
                                          float bx, float by, float bz) {
    float dx = ax - bx, dy = ay - by, dz = az - bz;
    return fmaf(dx, dx, fmaf(dy, dy, dz * dz));
}

__device__ __forceinline__ float warp_sum(float v) {
    #pragma unroll
    for (int o = 16; o > 0; o >>= 1) v += __shfl_down_sync(0xffffffffu, v, o);
    return v;
}

// last-block-out: after this block's g_acc contributions are complete
__device__ __forceinline__ void block_done(float* out) {
    __threadfence();
    cuda::atomic_ref<unsigned, cuda::thread_scope_device> dn(g_done);
    if (dn.fetch_add(1, cuda::memory_order_acq_rel) == TOTAL_BLKS - 1) {
        out[0] = (float)g_acc[0];
        out[1] = (float)(g_acc[1] / (double)(NB * NPTS * 4));
    }
}

// ============  Morton helpers  ============
__device__ __forceinline__ unsigned expandb(unsigned v) {
    v &= 1023u;
    v = (v | (v << 16)) & 0x030000FFu;
    v = (v | (v << 8))  & 0x0300F00Fu;
    v = (v | (v << 4))  & 0x030C30C3u;
    v = (v | (v << 2))  & 0x09249249u;
    return v;
}
__device__ __forceinline__ int bucket_of(int bx, int by, int bz) {
    unsigned m = expandb((unsigned)(bx << 3))
               | (expandb((unsigned)(by << 2)) << 1)
               | (expandb((unsigned)(bz << 2)) << 2);
    return (int)(m >> 7);
}
__device__ __forceinline__ void cell_range(float q, float r, int& c0, int& c1) {
    int lo = (int)floorf((q - r + 1.0f) * 32.0f) - 1;
    int hi = (int)floorf((q + r + 1.0f) * 32.0f) + 1;
    c0 = lo < 0 ? 0 : (lo > 63 ? 63 : lo);
    c1 = hi < 0 ? 0 : (hi > 63 ? 63 : hi);
}

// ============  Morton counting sort (2048 buckets): one block/batch  ============
__global__ void __launch_bounds__(1024, 1)
sort_kernel(const float* __restrict__ pcd) {
    __shared__ unsigned codes[NPTS];              // 32 KB: (bucket<<13)|orig_idx
    __shared__ int hist[NBKT];                    // 8 KB
    __shared__ int wsum[32];
    const int b    = blockIdx.x;
    const int tid  = threadIdx.x;
    const int lane = tid & 31;
    const int w    = tid >> 5;
    const float* P = pcd + b * NPTS * 3;

    if (b == 0 && tid == 0) { g_acc[0] = 0.0; g_acc[1] = 0.0; g_done = 0u; }
    if (tid == 0) g_bktoff[b*(NBKT+1) + NBKT] = NPTS;   // sentinel

    for (int i = tid; i < NBKT; i += 1024) hist[i] = 0;
    __syncthreads();

    for (int j = tid; j < NPTS; j += 1024) {
        float x = P[3*j], y = P[3*j+1], z = P[3*j+2];
        g_pcd4[b*NPTS + j] = make_float4(x, y, z, 0.0f);
        unsigned ux = (unsigned)fminf(fmaxf((x + 1.0f) * 32.0f, 0.0f), 63.0f);
        unsigned uy = (unsigned)fminf(fmaxf((y + 1.0f) * 32.0f, 0.0f), 63.0f);
        unsigned uz = (unsigned)fminf(fmaxf((z + 1.0f) * 32.0f, 0.0f), 63.0f);
        unsigned m = expandb(ux) | (expandb(uy) << 1) | (expandb(uz) << 2); // 18 bits
        unsigned bkt = m >> 7;                    // 11-bit bucket
        codes[j] = (bkt << 13) | (unsigned)j;
        atomicAdd(&hist[bkt], 1);
    }
    __syncthreads();

    int base = tid * 2;
    int s0 = hist[base], s1 = hist[base+1];
    int tsum = s0 + s1;
    int scan = tsum;
    #pragma unroll
    for (int o = 1; o < 32; o <<= 1) {
        int v = __shfl_up_sync(0xffffffffu, scan, o);
        if (lane >= o) scan += v;
    }
    if (lane == 31) wsum[w] = scan;
    __syncthreads();
    if (w == 0) {
        int v = wsum[lane], s = v;
        #pragma unroll
        for (int o = 1; o < 32; o <<= 1) {
            int t = __shfl_up_sync(0xffffffffu, s, o);
            if (lane >= o) s += t;
        }
        wsum[lane] = s - v;
    }
    __syncthreads();
    int excl = wsum[w] + (scan - tsum);
    hist[base]   = excl;
    hist[base+1] = excl + s0;
    g_bktoff[b*(NBKT+1) + base]     = excl;
    g_bktoff[b*(NBKT+1) + base + 1] = excl + s0;
    __syncthreads();

    for (int j = tid; j < NPTS; j += 1024) {
        unsigned c = codes[j];
        int bkt = (int)(c >> 13);
        int src = (int)(c & 0x1FFFu);
        int pos = atomicAdd(&hist[bkt], 1);
        float4 f = g_pcd4[b*NPTS + src];
        f.w = __int_as_float(src);
        g_sorted[b*NPTS + pos] = f;
    }
}

// ======  FPS v2: 4 warps, 64 pts/lane, 2-level AABB prune, smem coords  ======
__global__ void __launch_bounds__(FTH, 1)
fps_kernel(const float* __restrict__ pcd) {
    extern __shared__ float4 sc[];                // [NPTS] sorted coords, 128 KB
    __shared__ unsigned long long skey[2][4];     // double-buffered warp keys

    const int b    = blockIdx.x;
    const int tid  = threadIdx.x;
    const int w    = tid >> 5;                    // 0..3
    const int lane = tid & 31;
    const float4* S = g_sorted + b * NPTS;
    const float*  P = pcd + b * NPTS * 3;

    for (int j = tid; j < NPTS; j += FTH) sc[j] = S[j];
    __syncthreads();

    const int base = tid * 64;                    // 64 contiguous sorted pts
    float dist[64];
    #pragma unroll
    for (int k = 0; k < 64; k++) dist[k] = 1e10f;

    // 8 group AABBs + initial keys (key low = (8191-oi)<<13 | sorted_pos)
    float glox[8], ghix[8], gloy[8], ghiy[8], gloz[8], ghiz[8];
    float gdmax[8];
    unsigned long long gkey[8];
    #pragma unroll
    for (int g = 0; g < 8; g++) {
        float lx = 1e30f, hx = -1e30f, ly = 1e30f, hy = -1e30f;
        float lz = 1e30f, hz = -1e30f;
        unsigned best = 0;
        #pragma unroll
        for (int k = 0; k < 8; k++) {
            float4 f = sc[base + g*8 + k];
            lx = fminf(lx, f.x); hx = fmaxf(hx, f.x);
            ly = fminf(ly, f.y); hy = fmaxf(hy, f.y);
            lz = fminf(lz, f.z); hz = fmaxf(hz, f.z);
            unsigned lo = ((8191u - (unsigned)__float_as_int(f.w)) << 13)
                          | (unsigned)(base + g*8 + k);
            best = lo > best ? lo : best;
        }
        glox[g] = lx; ghix[g] = hx; gloy[g] = ly; ghiy[g] = hy;
        gloz[g] = lz; ghiz[g] = hz;
        gdmax[g] = 1e10f;
        gkey[g] = ((unsigned long long)__float_as_uint(1e10f) << 32) | best;
    }
    // lane AABB (over all 64 pts) + cached lane/warp keys
    float llox = glox[0], lhix = ghix[0], lloy = gloy[0], lhiy = ghiy[0];
    float lloz = gloz[0], lhiz = ghiz[0];
    unsigned long long lkey = gkey[0];
    #pragma unroll
    for (int g = 1; g < 8; g++) {
        llox = fminf(llox, glox[g]); lhix = fmaxf(lhix, ghix[g]);
        lloy = fminf(lloy, gloy[g]); lhiy = fmaxf(lhiy, ghiy[g]);
        lloz = fminf(lloz, gloz[g]); lhiz = fmaxf(lhiz, ghiz[g]);
        lkey = gkey[g] > lkey ? gkey[g] : lkey;
    }
    float ldmax = 1e10f;
    unsigned long long wkey = 0ull;

    float fx = P[0], fy = P[1], fz = P[2];        // far_0 = original index 0
    if (tid == 0) {
        g_newxyz[b*NPOINT*3 + 0] = fx;
        g_newxyz[b*NPOINT*3 + 1] = fy;
        g_newxyz[b*NPOINT*3 + 2] = fz;
    }
    __syncthreads();

    for (int s = 1; s < NPOINT; s++) {
        const int p = s & 1;
        // lane-level lower bound (64-pt AABB), deflated for fp safety
        float ax = fmaxf(fmaxf(llox - fx, fx - lhix), 0.0f);
        float ay = fmaxf(fmaxf(lloy - fy, fy - lhiy), 0.0f);
        float az = fmaxf(fmaxf(lloz - fz, fz - lhiz), 0.0f);
        float lb = (ax*ax + ay*ay + az*az) * 0.999f;
        bool lact = lb < ldmax;

        if (__ballot_sync(0xffffffffu, lact)) {
            if (lact) {
                bool upd = false;
                #pragma unroll
                for (int g = 0; g < 8; g++) {
                    float gx = fmaxf(fmaxf(glox[g] - fx, fx - ghix[g]), 0.0f);
                    float gy = fmaxf(fmaxf(gloy[g] - fy, fy - ghiy[g]), 0.0f);
                    float gz = fmaxf(fmaxf(gloz[g] - fz, fz - ghiz[g]), 0.0f);
                    float glb = (gx*gx + gy*gy + gz*gz) * 0.999f;
                    if (glb < gdmax[g]) {
                        unsigned long long kmax = 0ull;
                        #pragma unroll
                        for (int k = 0; k < 8; k++) {
                            float4 f = sc[base + g*8 + k];
                            float d  = sqdist_rn(f.x, f.y, f.z, fx, fy, fz);
                            float nd = fminf(dist[g*8+k], d);
                            dist[g*8+k] = nd;
                            unsigned lo =
                                ((8191u - (unsigned)__float_as_int(f.w)) << 13)
                                | (unsigned)(base + g*8 + k);
                            unsigned long long kk =
                                ((unsigned long long)__float_as_uint(nd) << 32) | lo;
                            kmax = kk > kmax ? kk : kmax;
                        }
                        gkey[g]  = kmax;
                        gdmax[g] = __uint_as_float((unsigned)(kmax >> 32));
                        upd = true;
                    }
                }
                if (upd) {
                    unsigned long long lk = gkey[0];
                    #pragma unroll
                    for (int g = 1; g < 8; g++) lk = gkey[g] > lk ? gkey[g] : lk;
                    lkey  = lk;
                    ldmax = __uint_as_float((unsigned)(lk >> 32));
                }
            }
            // warp argmax over lane keys (cached for pruned lanes)
            unsigned vb = (unsigned)(lkey >> 32);
            unsigned m  = __reduce_max_sync(0xffffffffu, vb);
            unsigned lo = (vb == m) ? (unsigned)lkey : 0u;
            unsigned l  = __reduce_max_sync(0xffffffffu, lo);
            wkey = ((unsigned long long)m << 32) | l;
        }
        if (lane == 0) skey[p][w] = wkey;         // unconditional (double buffer)
        __syncthreads();
        // every warp redundantly reduces the 4 warp keys (single barrier)
        unsigned long long k = skey[p][lane & 3];
        unsigned hi2 = (unsigned)(k >> 32);
        unsigned m2  = __reduce_max_sync(0xffffffffu, hi2);
        unsigned lo2 = (hi2 == m2) ? (unsigned)k : 0u;
        unsigned l2  = __reduce_max_sync(0xffffffffu, lo2);
        int pos = (int)(l2 & 0x1FFFu);
        float4 c = sc[pos];                       // same addr warp-wide: broadcast
        fx = c.x; fy = c.y; fz = c.z;
        if (tid == 0) {
            g_newxyz[(b*NPOINT + s)*3 + 0] = fx;
            g_newxyz[(b*NPOINT + s)*3 + 1] = fy;
            g_newxyz[(b*NPOINT + s)*3 + 2] = fz;
        }
    }
}

// ============  Repulsion: one thread per query, bucket gather  ============
#define INSERT5(dv) do {                                   \
    float _d = (dv);                                       \
    if (_d < s4) { s4 = _d;                                \
        if (s4 < s3) { float _t = s3; s3 = s4; s4 = _t; }  \
        if (s3 < s2) { float _t = s2; s2 = s3; s3 = _t; }  \
        if (s2 < s1) { float _t = s1; s1 = s2; s2 = _t; }  \
        if (s1 < s0) { float _t = s0; s0 = s1; s1 = _t; }  \
    } } while (0)

__global__ void __launch_bounds__(RBLK)
repulsion_kernel(float r2, float radius, float hh, float* out) {
    const int blocks_per_b = NPTS / RBLK;         // 32
    const int b  = blockIdx.x / blocks_per_b;
    const int qi = (blockIdx.x % blocks_per_b) * RBLK + threadIdx.x;
    const float4* P4 = g_pcd4 + b * NPTS;
    const float4* S  = g_sorted + b * NPTS;
    const int*    BO = g_bktoff + b * (NBKT+1);

    float4 q = P4[qi];
    const float qx = q.x, qy = q.y, qz = q.z;

    float s0 = 1e30f, s1 = 1e30f, s2 = 1e30f, s3 = 1e30f, s4 = 1e30f;
    int   c = 0, minidx = 0x7fffffff;
    float h0 = 0.0f;

    int cx0, cx1, cy0, cy1, cz0, cz1;
    cell_range(qx, radius, cx0, cx1);
    cell_range(qy, radius, cy0, cy1);
    cell_range(qz, radius, cz0, cz1);
    int bx0 = cx0 >> 3, bx1 = cx1 >> 3;
    int by0 = cy0 >> 2, by1 = cy1 >> 2;
    int bz0 = cz0 >> 2, bz1 = cz1 >> 2;

    for (int bz = bz0; bz <= bz1; bz++)
        for (int by = by0; by <= by1; by++)
            for (int bx = bx0; bx <= bx1; bx++) {
                int id = bucket_of(bx, by, bz);
                int s = BO[id], e = BO[id+1];
                for (int j = s; j < e; j++) {
                    float4 f = S[j];
                    float d = sqdist_f(f.x, f.y, f.z, qx, qy, qz);
                    if (d <= r2) {
                        c++;
                        int oi = __float_as_int(f.w);
                        if (oi < minidx) { minidx = oi; h0 = d; }
                        INSERT5(d);
                    }
                }
            }

    if (c > 20) {
        s0 = s1 = s2 = s3 = s4 = 1e30f; c = 0; h0 = 0.0f;
        for (int j = 0; j < NPTS; j++) {
            float4 f = P4[j];
            float d = sqdist_f(f.x, f.y, f.z, qx, qy, qz);
            if (d <= r2 && c < 20) {
                if (c == 0) h0 = d;
                c++;
                INSERT5(d);
            }
        }
    }

    int pads = 20 - c;
    if (pads > 5) pads = 5;
    for (int k = 0; k < pads; k++) INSERT5(h0);

    float acc = 0.0f;
    acc += radius - sqrtf(s1) * expf(-(s1 / hh));
    acc += radius - sqrtf(s2) * expf(-(s2 / hh));
    acc += radius - sqrtf(s3) * expf(-(s3 / hh));
    acc += radius - sqrtf(s4) * expf(-(s4 / hh));

    float ws = warp_sum(acc);
    __shared__ float red[RBLK/32];
    if ((threadIdx.x & 31) == 0) red[threadIdx.x >> 5] = ws;
    __syncthreads();
    if (threadIdx.x == 0) {
        float tot = 0.0f;
        #pragma unroll
        for (int w = 0; w < RBLK/32; w++) tot += red[w];
        atomicAdd(&g_acc[1], (double)tot);
        block_done(out);
    }
}

// ======  Uniform loss: one BLOCK per center, bucket gather + lane-per-hit eval  ======
struct ULevels {
    float  r2[5];
    float  el[5];
    float  den[5];
    double w[5];
    int    ns[5];
    float  rmax;
};

__device__ double eval_level_fast(float x, float y, float z, float d, unsigned idx,
                                  int cnt, float r2k, float el, float den, int ns,
                                  int lane, double wk)
{
    bool fk = (d <= r2k);
    unsigned bal = __ballot_sync(0xffffffffu, fk);
    int u = __popc(bal);
    unsigned fidx = __reduce_min_sync(0xffffffffu, fk ? idx : 0x7fffffffu);
    float m1 = 1e30f;
    for (int j = 0; j < cnt; j++) {
        float dj = __shfl_sync(0xffffffffu, d, j);
        float xj = __shfl_sync(0xffffffffu, x, j);
        float yj = __shfl_sync(0xffffffffu, y, j);
        float zj = __shfl_sync(0xffffffffu, z, j);
        if (dj <= r2k && j != lane)
            m1 = fminf(m1, sqdist_f(xj, yj, zj, x, y, z));
    }
    double acc = 0.0;
    if (lane == 0) {
        float t = sqrtf(1e-8f) - el;
        acc += wk * (double)((float)(ns - u + 1) * ((t * t) / den));
    }
    if (fk && idx != fidx) {
        float ud = sqrtf(fabsf(m1 + 1e-8f));
        float t  = ud - el;
        acc += wk * (double)((t * t) / den);
    }
    return acc;
}

__device__ float eval_level(const float4* H, int n_stored, int true_cnt,
                            float r2, float el, float den, int ns, int lane)
{
    int u = true_cnt < ns ? true_cnt : ns;
    float lsum = 0.0f;
    int jstart = 0;
    if (u < ns) {
        if (lane == 0) {
            float ud = sqrtf(1e-8f);
            float t  = ud - el;
            lsum += (float)(ns - u + 1) * ((t * t) / den);
        }
        jstart = 1;
    }
    for (int j = jstart + lane; j < u; j += 32) {
        float xj = 0.f, yj = 0.f, zj = 0.f;
        int seen = 0;
        for (int i = 0; i < n_stored; i++) {
            float4 h = H[i];
            if (h.w <= r2) {
                if (seen == j) { xj = h.x; yj = h.y; zj = h.z; break; }
                seen++;
            }
        }
        float m1 = 1e30f;
        seen = 0;
        for (int i = 0; i < n_stored && seen < u; i++) {
            float4 h = H[i];
            if (h.w <= r2) {
                if (seen != j) {
                    float d = sqdist_f(h.x, h.y, h.z, xj, yj, zj);
                    m1 = fminf(m1, d);
                }
                seen++;
            }
        }
        float ud = sqrtf(fabsf(m1 + 1e-8f));
        float t  = ud - el;
        lsum += (t * t) / den;
    }
    return lsum;
}

__global__ void __launch_bounds__(128)
uniform_kernel(ULevels L, float* out) {
    const int g    = blockIdx.x;
    const int b    = g / NPOINT;
    const int tid  = threadIdx.x;
    const int w    = tid >> 5;                    // 0..3
    const int lane = tid & 31;
    const float4* P4 = g_pcd4 + b * NPTS;
    const float4* S  = g_sorted + b * NPTS;
    const int*    BO = g_bktoff + b * (NBKT+1);

    const float qx = g_newxyz[g*3], qy = g_newxyz[g*3+1], qz = g_newxyz[g*3+2];
    const float r2max = L.r2[4];

    __shared__ float4 H[64];
    __shared__ int    hidx[64];
    __shared__ int    scnt;
    if (tid == 0) scnt = 0;
    __syncthreads();

    if (w == 0) {
        int cx0, cx1, cy0, cy1, cz0, cz1;
        cell_range(qx, L.rmax, cx0, cx1);
        cell_range(qy, L.rmax, cy0, cy1);
        cell_range(qz, L.rmax, cz0, cz1);
        int bx0 = cx0 >> 3, nx = (cx1 >> 3) - bx0 + 1;
        int by0 = cy0 >> 2, ny = (cy1 >> 2) - by0 + 1;
        int bz0 = cz0 >> 2, nz = (cz1 >> 2) - bz0 + 1;
        int nb = nx * ny * nz;                    // <= 48
        for (int t = lane; t < nb; t += 32) {
            int bx = bx0 + (t % nx);
            int rem = t / nx;
            int by = by0 + (rem % ny);
            int bz = bz0 + (rem / ny);
            int id = bucket_of(bx, by, bz);
            int s = BO[id], e = BO[id+1];
            for (int j = s; j < e; j++) {
                float4 f = S[j];
                float d = sqdist_f(f.x, f.y, f.z, qx, qy, qz);
                if (d <= r2max) {
                    int pos = atomicAdd(&scnt, 1);
                    if (pos < 64) {
                        H[pos] = make_float4(f.x, f.y, f.z, d);
                        hidx[pos] = __float_as_int(f.w);
                    }
                }
            }
        }
    }
    __syncthreads();
    int cnt = scnt;

    if (cnt <= 31) {
        float x = 0.f, y = 0.f, z = 0.f, d = 1e30f;
        unsigned idx = 0x7fffffffu;
        if (lane < cnt) {
            float4 h = H[lane];
            x = h.x; y = h.y; z = h.z; d = h.w;
            idx = (unsigned)hidx[lane];
        }
        double acc = 0.0;
        if (w == 0) {
            acc += eval_level_fast(x, y, z, d, idx, cnt, L.r2[0], L.el[0],
                                   L.den[0], L.ns[0], lane, L.w[0]);
            acc += eval_level_fast(x, y, z, d, idx, cnt, L.r2[1], L.el[1],
                                   L.den[1], L.ns[1], lane, L.w[1]);
        } else {
            int k = w + 1;                        // 2,3,4
            acc += eval_level_fast(x, y, z, d, idx, cnt, L.r2[k], L.el[k],
                                   L.den[k], L.ns[k], lane, L.w[k]);
        }
        #pragma unroll
        for (int o = 16; o > 0; o >>= 1)
            acc += __shfl_down_sync(0xffffffffu, acc, o);
        if (lane == 0 && acc != 0.0) atomicAdd(&g_acc[0], acc);
    } else {
        __shared__ float4 HF[256];
        if (w == 0) {
            double acc = 0.0;
            for (int k = 0; k < 5; k++) {
                float r2 = L.r2[k];
                int ns = L.ns[k];
                int c = 0;
                for (int it = 0; it < NPTS/32; it++) {
                    int j = it*32 + lane;
                    float4 f = P4[j];
                    float d = sqdist_f(f.x, f.y, f.z, qx, qy, qz);
                    bool hit = (d <= r2);
                    unsigned m = __ballot_sync(0xffffffffu, hit);
                    if (hit) {
                        int pos = c + __popc(m & ((1u << lane) - 1u));
                        if (pos < ns) HF[pos] = make_float4(f.x, f.y, f.z, d);
                    }
                    c += __popc(m);
                }
                int stored = c < ns ? c : ns;
                float lsum = eval_level(HF, stored, c, r2, L.el[k], L.den[k],
                                        ns, lane);
                acc += L.w[k] * (double)lsum;
            }
            #pragma unroll
            for (int o = 16; o > 0; o >>= 1)
                acc += __shfl_down_sync(0xffffffffu, acc, o);
            if (lane == 0) atomicAdd(&g_acc[0], acc);
        }
    }

    __syncthreads();
    if (tid == 0) block_done(out);
}

// ============================  launch  ============================
#define FPS_SMEM (NPTS * sizeof(float4))   /* 128 KB */

static cudaStream_t g_s2;
static cudaEvent_t  g_ev0, g_ev1;
struct _StreamInit {
    _StreamInit() {
        cudaStreamCreateWithFlags(&g_s2, cudaStreamNonBlocking);
        cudaEventCreateWithFlags(&g_ev0, cudaEventDisableTiming);
        cudaEventCreateWithFlags(&g_ev1, cudaEventDisableTiming);
        cudaFuncSetAttribute(fps_kernel,
                             cudaFuncAttributeMaxDynamicSharedMemorySize,
                             (int)FPS_SMEM);
    }
};
static _StreamInit g_stream_init;

extern "C" void kernel_launch(void* const* d_in, const int* in_sizes, int n_in,
                              void* d_out, int out_size) {
    const float* pcd = (const float*)d_in[0];
    float* out = (float*)d_out;

    sort_kernel<<<NB, 1024>>>(pcd);              // zeroes g_acc/g_done, fills buckets

    cudaEventRecord(g_ev0, 0);
    cudaStreamWaitEvent(g_s2, g_ev0, 0);
    {
        float r2     = (float)(0.07 * 0.07);
        float radius = (float)0.07;
        float hh     = (float)(0.03 * 0.03);
        repulsion_kernel<<<NBLK_REP, RBLK, 0, g_s2>>>(r2, radius, hh, out);
    }
    cudaEventRecord(g_ev1, g_s2);

    fps_kernel<<<NB, FTH, FPS_SMEM>>>(pcd);

    {
        static const double PS[5] = {0.004, 0.008, 0.01, 0.012, 0.016};
        ULevels L;
        for (int k = 0; k < 5; k++) {
            double p  = PS[k];
            int    ns = (int)(8192.0 * p);
            double r  = sqrt(p * 1.0);
            double disk = M_PI * 1.0 * p / (double)ns;
            double el   = sqrt(2.0 * disk / 1.732);
            L.r2[k]  = (float)(r * r);
            L.el[k]  = (float)el;
            L.den[k] = (float)(el + 1e-8);
            L.w[k]   = (p * 100.0) * (p * 100.0) / ((double)NG * (double)ns) / 5.0;
            L.ns[k]  = ns;
        }
        L.rmax = (float)sqrt(0.016);
        uniform_kernel<<<NG, 128>>>(L, out);
    }

    cudaStreamWaitEvent(0, g_ev1, 0);
}

// round 17
// speedup vs baseline: 2.3305x; 2.3305x over previous
#include <cuda_runtime.h>
#include <cuda/atomic>
#include <math.h>

#define NB     4
#define NPTS   8192
#define NPOINT 409          /* int(8192*0.05) */
#define NG     (NB*NPOINT)  /* 1636 */
#define NBKT   2048         /* counting-sort buckets (11-bit Morton prefix) */
#define RBLK   256
#define NBLK_REP (NB*(NPTS/RBLK))    /* 128 */
#define TOTAL_BLKS (NG + NBLK_REP)   /* 1764 */

// ---------------- device scratch (no allocations allowed) ----------------
__device__ double g_acc[2];                   // [0]=uniform, [1]=repulsion sum
__device__ float  g_newxyz[NB*NPOINT*3];      // FPS centers
__device__ float4 g_sorted[NB*NPTS];          // Morton-bucketed points (w = orig idx)
__device__ float4 g_pcd4[NB*NPTS];            // original-order points, float4
__device__ int    g_bktoff[NB*(NBKT+1)];      // bucket start offsets + sentinel
__device__ unsigned g_done;                   // completion counter

// exact-rounding distance (FPS argmax must match reference exactly)
__device__ __forceinline__ float sqdist_rn(float ax, float ay, float az,
                                           float bx, float by, float bz) {
    float dx = __fadd_rn(ax, -bx);
    float dy = __fadd_rn(ay, -by);
    float dz = __fadd_rn(az, -bz);
    return __fadd_rn(__fadd_rn(__fmul_rn(dx, dx), __fmul_rn(dy, dy)),
                     __fmul_rn(dz, dz));
}
// fast distance (FMA) — continuous-use sites only
__device__ __forceinline__ float sqdist_f(float ax, float ay, float az,
                                          float bx, float by, float bz) {
    float dx = ax - bx, dy = ay - by, dz = az - bz;
    return fmaf(dx, dx, fmaf(dy, dy, dz * dz));
}

__device__ __forceinline__ float warp_sum(float v) {
    #pragma unroll
    for (int o = 16; o > 0; o >>= 1) v += __shfl_down_sync(0xffffffffu, v, o);
    return v;
}

// last-block-out: after this block's g_acc contributions are complete
__device__ __forceinline__ void block_done(float* out) {
    __threadfence();
    cuda::atomic_ref<unsigned, cuda::thread_scope_device> dn(g_done);
    if (dn.fetch_add(1, cuda::memory_order_acq_rel) == TOTAL_BLKS - 1) {
        out[0] = (float)g_acc[0];
        out[1] = (float)(g_acc[1] / (double)(NB * NPTS * 4));
    }
}

// ============  Morton helpers  ============
__device__ __forceinline__ unsigned expandb(unsigned v) {
    v &= 1023u;
    v = (v | (v << 16)) & 0x030000FFu;
    v = (v | (v << 8))  & 0x0300F00Fu;
    v = (v | (v << 4))  & 0x030C30C3u;
    v = (v | (v << 2))  & 0x09249249u;
    return v;
}
__device__ __forceinline__ int bucket_of(int bx, int by, int bz) {
    unsigned m = expandb((unsigned)(bx << 3))
               | (expandb((unsigned)(by << 2)) << 1)
               | (expandb((unsigned)(bz << 2)) << 2);
    return (int)(m >> 7);
}
__device__ __forceinline__ void cell_range(float q, float r, int& c0, int& c1) {
    int lo = (int)floorf((q - r + 1.0f) * 32.0f) - 1;
    int hi = (int)floorf((q + r + 1.0f) * 32.0f) + 1;
    c0 = lo < 0 ? 0 : (lo > 63 ? 63 : lo);
    c1 = hi < 0 ? 0 : (hi > 63 ? 63 : hi);
}

// ============  Morton counting sort (2048 buckets): one block/batch  ============
__global__ void __launch_bounds__(1024, 1)
sort_kernel(const float* __restrict__ pcd) {
    __shared__ unsigned codes[NPTS];              // 32 KB: (bucket<<13)|orig_idx
    __shared__ int hist[NBKT];                    // 8 KB
    __shared__ int wsum[32];
    const int b    = blockIdx.x;
    const int tid  = threadIdx.x;
    const int lane = tid & 31;
    const int w    = tid >> 5;
    const float* P = pcd + b * NPTS * 3;

    if (b == 0 && tid == 0) { g_acc[0] = 0.0; g_acc[1] = 0.0; g_done = 0u; }
    if (tid == 0) g_bktoff[b*(NBKT+1) + NBKT] = NPTS;   // sentinel

    for (int i = tid; i < NBKT; i += 1024) hist[i] = 0;
    __syncthreads();

    for (int j = tid; j < NPTS; j += 1024) {
        float x = P[3*j], y = P[3*j+1], z = P[3*j+2];
        g_pcd4[b*NPTS + j] = make_float4(x, y, z, 0.0f);
        unsigned ux = (unsigned)fminf(fmaxf((x + 1.0f) * 32.0f, 0.0f), 63.0f);
        unsigned uy = (unsigned)fminf(fmaxf((y + 1.0f) * 32.0f, 0.0f), 63.0f);
        unsigned uz = (unsigned)fminf(fmaxf((z + 1.0f) * 32.0f, 0.0f), 63.0f);
        unsigned m = expandb(ux) | (expandb(uy) << 1) | (expandb(uz) << 2); // 18 bits
        unsigned bkt = m >> 7;                    // 11-bit bucket
        codes[j] = (bkt << 13) | (unsigned)j;
        atomicAdd(&hist[bkt], 1);
    }
    __syncthreads();

    int base = tid * 2;
    int s0 = hist[base], s1 = hist[base+1];
    int tsum = s0 + s1;
    int scan = tsum;
    #pragma unroll
    for (int o = 1; o < 32; o <<= 1) {
        int v = __shfl_up_sync(0xffffffffu, scan, o);
        if (lane >= o) scan += v;
    }
    if (lane == 31) wsum[w] = scan;
    __syncthreads();
    if (w == 0) {
        int v = wsum[lane], s = v;
        #pragma unroll
        for (int o = 1; o < 32; o <<= 1) {
            int t = __shfl_up_sync(0xffffffffu, s, o);
            if (lane >= o) s += t;
        }
        wsum[lane] = s - v;
    }
    __syncthreads();
    int excl = wsum[w] + (scan - tsum);
    hist[base]   = excl;
    hist[base+1] = excl + s0;
    g_bktoff[b*(NBKT+1) + base]     = excl;
    g_bktoff[b*(NBKT+1) + base + 1] = excl + s0;
    __syncthreads();

    for (int j = tid; j < NPTS; j += 1024) {
        unsigned c = codes[j];
        int bkt = (int)(c >> 13);
        int src = (int)(c & 0x1FFFu);
        int pos = atomicAdd(&hist[bkt], 1);
        float4 f = g_pcd4[b*NPTS + src];
        f.w = __int_as_float(src);
        g_sorted[b*NPTS + pos] = f;
    }
}

// ======  FPS (R15 skeleton + lane-level gate): 512 thr, 2×8-pt groups  ======
__global__ void __launch_bounds__(512, 1)
fps_kernel(const float* __restrict__ pcd) {
    extern __shared__ float4 ctab[];              // [NPTS] orig-index coords, 128 KB

    const int b    = blockIdx.x;
    const int tid  = threadIdx.x;
    const int w    = tid >> 5;                    // 0..15
    const int lane = tid & 31;
    const float4* S  = g_sorted + b * NPTS;
    const float4* P4 = g_pcd4  + b * NPTS;
    const float*  P  = pcd + b * NPTS * 3;

    for (int j = tid; j < NPTS; j += 512)
        ctab[j] = P4[j];

    // lane owns 16 CONTIGUOUS bucketed points [tid*16, tid*16+16) as 2 groups of 8
    float xs[16], ys[16], zs[16], dist[16];
    unsigned loid[16];                            // 8191 - orig_idx
    #pragma unroll
    for (int k = 0; k < 16; k++) {
        float4 f = S[tid*16 + k];
        xs[k] = f.x; ys[k] = f.y; zs[k] = f.z;
        dist[k] = 1e10f;
        loid[k] = 8191u - (unsigned)__float_as_int(f.w);
    }

    // per-group AABBs
    float lox0=xs[0],hix0=xs[0],loy0=ys[0],hiy0=ys[0],loz0=zs[0],hiz0=zs[0];
    float lox1=xs[8],hix1=xs[8],loy1=ys[8],hiy1=ys[8],loz1=zs[8],hiz1=zs[8];
    #pragma unroll
    for (int k = 1; k < 8; k++) {
        lox0=fminf(lox0,xs[k]);   hix0=fmaxf(hix0,xs[k]);
        loy0=fminf(loy0,ys[k]);   hiy0=fmaxf(hiy0,ys[k]);
        loz0=fminf(loz0,zs[k]);   hiz0=fmaxf(hiz0,zs[k]);
        lox1=fminf(lox1,xs[8+k]); hix1=fmaxf(hix1,xs[8+k]);
        loy1=fminf(loy1,ys[8+k]); hiy1=fmaxf(hiy1,ys[8+k]);
        loz1=fminf(loz1,zs[8+k]); hiz1=fmaxf(hiz1,zs[8+k]);
    }
    // lane-level AABB (union of the two groups)
    const float llox = fminf(lox0, lox1), lhix = fmaxf(hix0, hix1);
    const float lloy = fminf(loy0, loy1), lhiy = fmaxf(hiy0, hiy1);
    const float lloz = fminf(loz0, loz1), lhiz = fmaxf(hiz0, hiz1);

    // per-group cached keys (max dist | tie-break) and lane key
    unsigned long long gkey0, gkey1, lkey;
    {
        unsigned b0 = 0, b1 = 0;
        #pragma unroll
        for (int k = 0; k < 8; k++) {
            b0 = loid[k]   > b0 ? loid[k]   : b0;
            b1 = loid[8+k] > b1 ? loid[8+k] : b1;
        }
        unsigned long long hi = (unsigned long long)__float_as_uint(1e10f) << 32;
        gkey0 = hi | b0; gkey1 = hi | b1;
        lkey  = gkey0 > gkey1 ? gkey0 : gkey1;
    }
    float dmax0 = 1e10f, dmax1 = 1e10f;

    __shared__ unsigned long long skey[32];
    if (tid < 32) skey[tid] = 0ull;               // lanes 16..31 stay 0 (never win)

    float fx = P[0], fy = P[1], fz = P[2];        // far_0 = original index 0
    if (tid == 0) {
        g_newxyz[b*NPOINT*3 + 0] = fx;
        g_newxyz[b*NPOINT*3 + 1] = fy;
        g_newxyz[b*NPOINT*3 + 2] = fz;
    }
    __syncthreads();

    for (int s = 1; s < NPOINT; s++) {
        // lane-level lower bound gates the two group tests
        float lax = fmaxf(fmaxf(llox - fx, fx - lhix), 0.0f);
        float lay = fmaxf(fmaxf(lloy - fy, fy - lhiy), 0.0f);
        float laz = fmaxf(fmaxf(lloz - fz, fz - lhiz), 0.0f);
        float llb = (lax*lax + lay*lay + laz*laz) * 0.999f;
        bool lact = llb < fmaxf(dmax0, dmax1);

        if (__ballot_sync(0xffffffffu, lact)) {
            if (lact) {
                float ax0 = fmaxf(fmaxf(lox0 - fx, fx - hix0), 0.0f);
                float ay0 = fmaxf(fmaxf(loy0 - fy, fy - hiy0), 0.0f);
                float az0 = fmaxf(fmaxf(loz0 - fz, fz - hiz0), 0.0f);
                bool a0 = (ax0*ax0 + ay0*ay0 + az0*az0) * 0.999f < dmax0;
                float ax1 = fmaxf(fmaxf(lox1 - fx, fx - hix1), 0.0f);
                float ay1 = fmaxf(fmaxf(loy1 - fy, fy - hiy1), 0.0f);
                float az1 = fmaxf(fmaxf(loz1 - fz, fz - hiz1), 0.0f);
                bool a1 = (ax1*ax1 + ay1*ay1 + az1*az1) * 0.999f < dmax1;
                if (a0) {
                    unsigned long long kmax = 0ull;
                    #pragma unroll
                    for (int k = 0; k < 8; k++) {
                        float d  = sqdist_rn(xs[k], ys[k], zs[k], fx, fy, fz);
                        float nd = fminf(dist[k], d);
                        dist[k]  = nd;
                        unsigned long long kk =
                            ((unsigned long long)__float_as_uint(nd) << 32) | loid[k];
                        kmax = kk > kmax ? kk : kmax;
                    }
                    gkey0 = kmax;
                    dmax0 = __uint_as_float((unsigned)(kmax >> 32));
                }
                if (a1) {
                    unsigned long long kmax = 0ull;
                    #pragma unroll
                    for (int k = 0; k < 8; k++) {
                        float d  = sqdist_rn(xs[8+k], ys[8+k], zs[8+k], fx, fy, fz);
                        float nd = fminf(dist[8+k], d);
                        dist[8+k] = nd;
                        unsigned long long kk =
                            ((unsigned long long)__float_as_uint(nd) << 32) | loid[8+k];
                        kmax = kk > kmax ? kk : kmax;
                    }
                    gkey1 = kmax;
                    dmax1 = __uint_as_float((unsigned)(kmax >> 32));
                }
                if (a0 | a1) lkey = gkey0 > gkey1 ? gkey0 : gkey1;
            }
            // warp argmax (cached lane keys for pruned lanes)
            unsigned vb = (unsigned)(lkey >> 32);
            unsigned m  = __reduce_max_sync(0xffffffffu, vb);
            unsigned lo = (vb == m) ? (unsigned)lkey : 0u;
            unsigned l  = __reduce_max_sync(0xffffffffu, lo);
            if (lane == 0)
                skey[w] = ((unsigned long long)m << 32) | l;
        }
        __syncthreads();
        // every warp redundantly reduces the 16 warp keys (no 2nd barrier)
        unsigned long long k = skey[lane];
        unsigned hi2 = (unsigned)(k >> 32);
        unsigned m2  = __reduce_max_sync(0xffffffffu, hi2);
        unsigned lo2 = (hi2 == m2) ? (unsigned)k : 0u;
        unsigned l2  = __reduce_max_sync(0xffffffffu, lo2);
        int oi = 8191 - (int)l2;
        float4 c = ctab[oi];                      // same addr warp-wide: broadcast
        fx = c.x; fy = c.y; fz = c.z;
        if (tid == 0) {
            g_newxyz[(b*NPOINT + s)*3 + 0] = fx;
            g_newxyz[(b*NPOINT + s)*3 + 1] = fy;
            g_newxyz[(b*NPOINT + s)*3 + 2] = fz;
        }
    }
}

// ============  Repulsion: one thread per query, bucket gather  ============
#define INSERT5(dv) do {                                   \
    float _d = (dv);                                       \
    if (_d < s4) { s4 = _d;                                \
        if (s4 < s3) { float _t = s3; s3 = s4; s4 = _t; }  \
        if (s3 < s2) { float _t = s2; s2 = s3; s3 = _t; }  \
        if (s2 < s1) { float _t = s1; s1 = s2; s2 = _t; }  \
        if (s1 < s0) { float _t = s0; s0 = s1; s1 = _t; }  \
    } } while (0)

__global__ void __launch_bounds__(RBLK)
repulsion_kernel(float r2, float radius, float hh, float* out) {
    const int blocks_per_b = NPTS / RBLK;         // 32
    const int b  = blockIdx.x / blocks_per_b;
    const int qi = (blockIdx.x % blocks_per_b) * RBLK + threadIdx.x;
    const float4* P4 = g_pcd4 + b * NPTS;
    const float4* S  = g_sorted + b * NPTS;
    const int*    BO = g_bktoff + b * (NBKT+1);

    float4 q = P4[qi];
    const float qx = q.x, qy = q.y, qz = q.z;

    float s0 = 1e30f, s1 = 1e30f, s2 = 1e30f, s3 = 1e30f, s4 = 1e30f;
    int   c = 0, minidx = 0x7fffffff;
    float h0 = 0.0f;

    int cx0, cx1, cy0, cy1, cz0, cz1;
    cell_range(qx, radius, cx0, cx1);
    cell_range(qy, radius, cy0, cy1);
    cell_range(qz, radius, cz0, cz1);
    int bx0 = cx0 >> 3, bx1 = cx1 >> 3;
    int by0 = cy0 >> 2, by1 = cy1 >> 2;
    int bz0 = cz0 >> 2, bz1 = cz1 >> 2;

    for (int bz = bz0; bz <= bz1; bz++)
        for (int by = by0; by <= by1; by++)
            for (int bx = bx0; bx <= bx1; bx++) {
                int id = bucket_of(bx, by, bz);
                int s = BO[id], e = BO[id+1];
                for (int j = s; j < e; j++) {
                    float4 f = S[j];
                    float d = sqdist_f(f.x, f.y, f.z, qx, qy, qz);
                    if (d <= r2) {
                        c++;
                        int oi = __float_as_int(f.w);
                        if (oi < minidx) { minidx = oi; h0 = d; }
                        INSERT5(d);
                    }
                }
            }

    if (c > 20) {
        s0 = s1 = s2 = s3 = s4 = 1e30f; c = 0; h0 = 0.0f;
        for (int j = 0; j < NPTS; j++) {
            float4 f = P4[j];
            float d = sqdist_f(f.x, f.y, f.z, qx, qy, qz);
            if (d <= r2 && c < 20) {
                if (c == 0) h0 = d;
                c++;
                INSERT5(d);
            }
        }
    }

    int pads = 20 - c;
    if (pads > 5) pads = 5;
    for (int k = 0; k < pads; k++) INSERT5(h0);

    float acc = 0.0f;
    acc += radius - sqrtf(s1) * expf(-(s1 / hh));
    acc += radius - sqrtf(s2) * expf(-(s2 / hh));
    acc += radius - sqrtf(s3) * expf(-(s3 / hh));
    acc += radius - sqrtf(s4) * expf(-(s4 / hh));

    float ws = warp_sum(acc);
    __shared__ float red[RBLK/32];
    if ((threadIdx.x & 31) == 0) red[threadIdx.x >> 5] = ws;
    __syncthreads();
    if (threadIdx.x == 0) {
        float tot = 0.0f;
        #pragma unroll
        for (int w = 0; w < RBLK/32; w++) tot += red[w];
        atomicAdd(&g_acc[1], (double)tot);
        block_done(out);
    }
}

// ======  Uniform loss: one BLOCK per center, 128-thr bucket gather  ======
struct ULevels {
    float  r2[5];
    float  el[5];
    float  den[5];
    double w[5];
    int    ns[5];
    float  rmax;
};

__device__ double eval_level_fast(float x, float y, float z, float d, unsigned idx,
                                  int cnt, float r2k, float el, float den, int ns,
                                  int lane, double wk)
{
    bool fk = (d <= r2k);
    unsigned bal = __ballot_sync(0xffffffffu, fk);
    int u = __popc(bal);
    unsigned fidx = __reduce_min_sync(0xffffffffu, fk ? idx : 0x7fffffffu);
    float m1 = 1e30f;
    for (int j = 0; j < cnt; j++) {
        float dj = __shfl_sync(0xffffffffu, d, j);
        float xj = __shfl_sync(0xffffffffu, x, j);
        float yj = __shfl_sync(0xffffffffu, y, j);
        float zj = __shfl_sync(0xffffffffu, z, j);
        if (dj <= r2k && j != lane)
            m1 = fminf(m1, sqdist_f(xj, yj, zj, x, y, z));
    }
    double acc = 0.0;
    if (lane == 0) {
        float t = sqrtf(1e-8f) - el;
        acc += wk * (double)((float)(ns - u + 1) * ((t * t) / den));
    }
    if (fk && idx != fidx) {
        float ud = sqrtf(fabsf(m1 + 1e-8f));
        float t  = ud - el;
        acc += wk * (double)((t * t) / den);
    }
    return acc;
}

__device__ float eval_level(const float4* H, int n_stored, int true_cnt,
                            float r2, float el, float den, int ns, int lane)
{
    int u = true_cnt < ns ? true_cnt : ns;
    float lsum = 0.0f;
    int jstart = 0;
    if (u < ns) {
        if (lane == 0) {
            float ud = sqrtf(1e-8f);
            float t  = ud - el;
            lsum += (float)(ns - u + 1) * ((t * t) / den);
        }
        jstart = 1;
    }
    for (int j = jstart + lane; j < u; j += 32) {
        float xj = 0.f, yj = 0.f, zj = 0.f;
        int seen = 0;
        for (int i = 0; i < n_stored; i++) {
            float4 h = H[i];
            if (h.w <= r2) {
                if (seen == j) { xj = h.x; yj = h.y; zj = h.z; break; }
                seen++;
            }
        }
        float m1 = 1e30f;
        seen = 0;
        for (int i = 0; i < n_stored && seen < u; i++) {
            float4 h = H[i];
            if (h.w <= r2) {
                if (seen != j) {
                    float d = sqdist_f(h.x, h.y, h.z, xj, yj, zj);
                    m1 = fminf(m1, d);
                }
                seen++;
            }
        }
        float ud = sqrtf(fabsf(m1 + 1e-8f));
        float t  = ud - el;
        lsum += (t * t) / den;
    }
    return lsum;
}

__global__ void __launch_bounds__(128)
uniform_kernel(ULevels L, float* out) {
    const int g    = blockIdx.x;
    const int b    = g / NPOINT;
    const int tid  = threadIdx.x;
    const int w    = tid >> 5;                    // 0..3
    const int lane = tid & 31;
    const float4* P4 = g_pcd4 + b * NPTS;
    const float4* S  = g_sorted + b * NPTS;
    const int*    BO = g_bktoff + b * (NBKT+1);

    const float qx = g_newxyz[g*3], qy = g_newxyz[g*3+1], qz = g_newxyz[g*3+2];
    const float r2max = L.r2[4];

    __shared__ float4 H[64];
    __shared__ int    hidx[64];
    __shared__ int    scnt;
    if (tid == 0) scnt = 0;
    __syncthreads();

    // ALL 128 threads gather hits (order in H arbitrary; fast path order-free)
    {
        int cx0, cx1, cy0, cy1, cz0, cz1;
        cell_range(qx, L.rmax, cx0, cx1);
        cell_range(qy, L.rmax, cy0, cy1);
        cell_range(qz, L.rmax, cz0, cz1);
        int bx0 = cx0 >> 3, nx = (cx1 >> 3) - bx0 + 1;
        int by0 = cy0 >> 2, ny = (cy1 >> 2) - by0 + 1;
        int bz0 = cz0 >> 2, nz = (cz1 >> 2) - bz0 + 1;
        int nb = nx * ny * nz;                    // <= 48
        for (int t = tid; t < nb; t += 128) {
            int bx = bx0 + (t % nx);
            int rem = t / nx;
            int by = by0 + (rem % ny);
            int bz = bz0 + (rem / ny);
            int id = bucket_of(bx, by, bz);
            int s = BO[id], e = BO[id+1];
            for (int j = s; j < e; j++) {
                float4 f = S[j];
                float d = sqdist_f(f.x, f.y, f.z, qx, qy, qz);
                if (d <= r2max) {
                    int pos = atomicAdd(&scnt, 1);
                    if (pos < 64) {
                        H[pos] = make_float4(f.x, f.y, f.z, d);
                        hidx[pos] = __float_as_int(f.w);
                    }
                }
            }
        }
    }
    __syncthreads();
    int cnt = scnt;

    if (cnt <= 31) {
        float x = 0.f, y = 0.f, z = 0.f, d = 1e30f;
        unsigned idx = 0x7fffffffu;
        if (lane < cnt) {
            float4 h = H[lane];
            x = h.x; y = h.y; z = h.z; d = h.w;
            idx = (unsigned)hidx[lane];
        }
        double acc = 0.0;
        if (w == 0) {
            acc += eval_level_fast(x, y, z, d, idx, cnt, L.r2[0], L.el[0],
                                   L.den[0], L.ns[0], lane, L.w[0]);
            acc += eval_level_fast(x, y, z, d, idx, cnt, L.r2[1], L.el[1],
                                   L.den[1], L.ns[1], lane, L.w[1]);
        } else {
            int k = w + 1;                        // 2,3,4
            acc += eval_level_fast(x, y, z, d, idx, cnt, L.r2[k], L.el[k],
                                   L.den[k], L.ns[k], lane, L.w[k]);
        }
        #pragma unroll
        for (int o = 16; o > 0; o >>= 1)
            acc += __shfl_down_sync(0xffffffffu, acc, o);
        if (lane == 0 && acc != 0.0) atomicAdd(&g_acc[0], acc);
    } else {
        __shared__ float4 HF[256];
        if (w == 0) {
            double acc = 0.0;
            for (int k = 0; k < 5; k++) {
                float r2 = L.r2[k];
                int ns = L.ns[k];
                int c = 0;
                for (int it = 0; it < NPTS/32; it++) {
                    int j = it*32 + lane;
                    float4 f = P4[j];
                    float d = sqdist_f(f.x, f.y, f.z, qx, qy, qz);
                    bool hit = (d <= r2);
                    unsigned m = __ballot_sync(0xffffffffu, hit);
                    if (hit) {
                        int pos = c + __popc(m & ((1u << lane) - 1u));
                        if (pos < ns) HF[pos] = make_float4(f.x, f.y, f.z, d);
                    }
                    c += __popc(m);
                }
                int stored = c < ns ? c : ns;
                float lsum = eval_level(HF, stored, c, r2, L.el[k], L.den[k],
                                        ns, lane);
                acc += L.w[k] * (double)lsum;
            }
            #pragma unroll
            for (int o = 16; o > 0; o >>= 1)
                acc += __shfl_down_sync(0xffffffffu, acc, o);
            if (lane == 0) atomicAdd(&g_acc[0], acc);
        }
    }

    __syncthreads();
    if (tid == 0) block_done(out);
}

// ============================  launch  ============================
#define FPS_SMEM (NPTS * sizeof(float4))   /* 128 KB */

static cudaStream_t g_s2;
static cudaEvent_t  g_ev0, g_ev1;
struct _StreamInit {
    _StreamInit() {
        cudaStreamCreateWithFlags(&g_s2, cudaStreamNonBlocking);
        cudaEventCreateWithFlags(&g_ev0, cudaEventDisableTiming);
        cudaEventCreateWithFlags(&g_ev1, cudaEventDisableTiming);
        cudaFuncSetAttribute(fps_kernel,
                             cudaFuncAttributeMaxDynamicSharedMemorySize,
                             (int)FPS_SMEM);
    }
};
static _StreamInit g_stream_init;

extern "C" void kernel_launch(void* const* d_in, const int* in_sizes, int n_in,
                              void* d_out, int out_size) {
    const float* pcd = (const float*)d_in[0];
    float* out = (float*)d_out;

    sort_kernel<<<NB, 1024>>>(pcd);              // zeroes g_acc/g_done, fills buckets

    cudaEventRecord(g_ev0, 0);
    cudaStreamWaitEvent(g_s2, g_ev0, 0);
    {
        float r2     = (float)(0.07 * 0.07);
        float radius = (float)0.07;
        float hh     = (float)(0.03 * 0.03);
        repulsion_kernel<<<NBLK_REP, RBLK, 0, g_s2>>>(r2, radius, hh, out);
    }
    cudaEventRecord(g_ev1, g_s2);

    fps_kernel<<<NB, 512, FPS_SMEM>>>(pcd);

    {
        static const double PS[5] = {0.004, 0.008, 0.01, 0.012, 0.016};
        ULevels L;
        for (int k = 0; k < 5; k++) {
            double p  = PS[k];
            int    ns = (int)(8192.0 * p);
            double r  = sqrt(p * 1.0);
            double disk = M_PI * 1.0 * p / (double)ns;
            double el   = sqrt(2.0 * disk / 1.732);
            L.r2[k]  = (float)(r * r);
            L.el[k]  = (float)el;
            L.den[k] = (float)(el + 1e-8);
            L.w[k]   = (p * 100.0) * (p * 100.0) / ((double)NG * (double)ns) / 5.0;
            L.ns[k]  = ns;
        }
        L.rmax = (float)sqrt(0.016);
        uniform_kernel<<<NG, 128>>>(L, out);
    }

    cudaStreamWaitEvent(0, g_ev1, 0);
}